// round 11
// baseline (speedup 1.0000x reference)
#include <cuda_runtime.h>

#define MM 512
#define NN 512
#define NPIX (MM*NN)

typedef unsigned long long u64;

__device__ float2 g_base[NPIX];   // {Xb, yb}
__device__ float2 g_det[NPIX];    // {Xd, yd - Xd}
__device__ unsigned g_bmin[1024], g_bmax[1024];

#define LOG2E 1.4426950408889634f

#define FMA2(d,a,b,c) asm("fma.rn.f32x2 %0, %1, %2, %3;" : "=l"(d) : "l"(a), "l"(b), "l"(c))
#define ADD2(d,a,b)   asm("add.rn.f32x2 %0, %1, %2;"     : "=l"(d) : "l"(a), "l"(b))
#define MUL2(d,a,b)   asm("mul.rn.f32x2 %0, %1, %2;"     : "=l"(d) : "l"(a), "l"(b))
#define PACK2(d,lo,hi) asm("mov.b64 %0, {%1, %2};" : "=l"(d) : "f"(lo), "f"(hi))
#define UNPACK2(lo,hi,s) asm("mov.b64 {%0, %1}, %2;" : "=f"(lo), "=f"(hi) : "l"(s))
__device__ __forceinline__ float ex2f(float a) {
    float r; asm("ex2.approx.f32 %0, %1;" : "=f"(r) : "f"(a)); return r;
}

__device__ __forceinline__ unsigned f2key(float f) {
    unsigned u = __float_as_uint(f);
    return (u & 0x80000000u) ? ~u : (u | 0x80000000u);
}
__device__ __forceinline__ float key2f(unsigned k) {
    unsigned u = (k & 0x80000000u) ? (k ^ 0x80000000u) : ~k;
    return __uint_as_float(u);
}

// ---- fused: 9x9 box (zero pad, /81) + detail + per-block y min/max ----
__global__ __launch_bounds__(256) void k_pre(const float* __restrict__ X,
                                             const float* __restrict__ Y) {
    __shared__ float2 raw[16][40];
    __shared__ float2 hs[16][32];
    __shared__ unsigned smn[8], smx[8];

    int tx = threadIdx.x, ty = threadIdx.y;
    int bx = blockIdx.x * 32, by = blockIdx.y * 8;
    int tid = ty * 32 + tx;

    for (int k = tid; k < 16 * 40; k += 256) {
        int r = k / 40, c = k % 40;
        int gi = by + r - 4, gj = bx + c - 4;
        float2 v = make_float2(0.f, 0.f);
        if ((unsigned)gi < 512u && (unsigned)gj < 512u) {
            int idx = (gi << 9) + gj;
            v = make_float2(X[idx], Y[idx]);
        }
        raw[r][c] = v;
    }
    __syncthreads();

    for (int k = tid; k < 16 * 32; k += 256) {
        int r = k >> 5, c = k & 31;
        float sx = 0.f, sy = 0.f;
        #pragma unroll
        for (int d = 0; d < 9; ++d) {
            float2 v = raw[r][c + d];
            sx += v.x; sy += v.y;
        }
        hs[r][c] = make_float2(sx, sy);
    }
    __syncthreads();

    float sx = 0.f, sy = 0.f;
    #pragma unroll
    for (int d = 0; d < 9; ++d) {
        float2 v = hs[ty + d][tx];
        sx += v.x; sy += v.y;
    }
    const float inv81 = 1.0f / 81.0f;
    float xb = sx * inv81, yb = sy * inv81;
    float2 ctr = raw[ty + 4][tx + 4];
    float xd = ctr.x - xb;
    float zd = (ctr.y - yb) - xd;
    int idx = ((by + ty) << 9) + bx + tx;
    g_base[idx] = make_float2(xb, yb);
    g_det[idx]  = make_float2(xd, zd);

    unsigned key = f2key(ctr.y);
    unsigned mn = key, mx = key;
    #pragma unroll
    for (int o = 16; o; o >>= 1) {
        mn = min(mn, __shfl_xor_sync(0xFFFFFFFFu, mn, o));
        mx = max(mx, __shfl_xor_sync(0xFFFFFFFFu, mx, o));
    }
    if ((tid & 31) == 0) { smn[tid >> 5] = mn; smx[tid >> 5] = mx; }
    __syncthreads();
    if (tid == 0) {
        unsigned m = smn[0], M = smx[0];
        #pragma unroll
        for (int w = 1; w < 8; ++w) { m = min(m, smn[w]); M = max(M, smx[w]); }
        int bid = blockIdx.y * 16 + blockIdx.x;
        g_bmin[bid] = m;
        g_bmax[bid] = M;
    }
}

// ================= main bilateral kernel =================
// Tile 32 cols x 16 rows, block 32x8 (256 thr), 2 center rows per thread.
// Overlapping-pair smem: s[r][c] = {v[c], v[c+1]}; consumer stride-2 LDS.64.
// Exponent in 3 packed ops: a = (C*v + b1)*v + (L + lr + C*x^2), b1 = -2Cx.
// Invalid rows carry sentinel x=1e19 -> a -> -inf -> w=0.
#define TROW 34      // 16 + 2*9
#define TCOL 50      // 32 + 2*9
#define DROW 20      // 16 + 2*2
#define DCOL 40      // 32 + 2*4

__global__ __launch_bounds__(256, 4) void k_main(const float* __restrict__ R,
                                                 float* __restrict__ out) {
    __shared__ float2 sbx[TROW][TCOL];
    __shared__ float2 sby[TROW][TCOL];
    __shared__ float2 sdx[DROW][DCOL];
    __shared__ float2 sdy[DROW][DCOL];
    __shared__ unsigned smn[8], smx[8];

    int tx = threadIdx.x, ty = threadIdx.y;   // 32 x 8
    int bx = blockIdx.x * 32, by = blockIdx.y * 16;
    int tid = ty * 32 + tx;

    // global min/max reduction from k_pre partials
    {
        unsigned mn = 0xFFFFFFFFu, mx = 0u;
        #pragma unroll
        for (int i = 0; i < 4; ++i) {
            int k = tid + 256 * i;
            mn = min(mn, g_bmin[k]);
            mx = max(mx, g_bmax[k]);
        }
        #pragma unroll
        for (int o = 16; o; o >>= 1) {
            mn = min(mn, __shfl_xor_sync(0xFFFFFFFFu, mn, o));
            mx = max(mx, __shfl_xor_sync(0xFFFFFFFFu, mx, o));
        }
        if ((tid & 31) == 0) { smn[tid >> 5] = mn; smx[tid >> 5] = mx; }
    }

    // Zero the never-filled last .y slots (kept finite; col mask forces w=0)
    if (tid < TROW) {
        sbx[tid][TCOL - 1].y = 0.f;
        sby[tid][TCOL - 1].y = 0.f;
    }
    if (tid < DROW) {
        sdx[tid][DCOL - 1].y = 0.f;
        sdy[tid][DCOL - 1].y = 0.f;
    }

    // Tile fill; out-of-range rows get sentinel x=1e19 (=> w=0), y=0
    for (int k = tid; k < TROW * TCOL; k += 256) {
        int r = k / TCOL, c = k % TCOL;
        int gi = by + r - 9;
        int gj = min(max(bx + c - 9, 0), 511);
        float vx = 1e19f, vy = 0.f;
        if ((unsigned)gi < 512u) {
            float2 v = g_base[(gi << 9) + gj];
            vx = v.x; vy = v.y;
        }
        sbx[r][c].x = vx;
        sby[r][c].x = vy;
        if (c > 0) { sbx[r][c - 1].y = vx; sby[r][c - 1].y = vy; }
    }
    for (int k = tid; k < DROW * DCOL; k += 256) {
        int r = k / DCOL, c = k % DCOL;
        int gi = by + r - 2;
        int gj = min(max(bx + c - 4, 0), 511);
        float vx = 1e19f, vy = 0.f;
        if ((unsigned)gi < 512u) {
            float2 v = g_det[(gi << 9) + gj];
            vx = v.x; vy = v.y;
        }
        sdx[r][c].x = vx;
        sdy[r][c].x = vy;
        if (c > 0) { sdx[r][c - 1].y = vx; sdy[r][c - 1].y = vy; }
    }
    __syncthreads();

    float Cs;
    {
        unsigned m = smn[0], M = smx[0];
        #pragma unroll
        for (int w = 1; w < 8; ++w) { m = min(m, smn[w]); M = max(M, smx[w]); }
        float sigma = R[0] * (key2f(M) - key2f(m));
        float h = sigma * 0.5f;
        Cs = -LOG2E / (h * h);
    }
    u64 C2; PACK2(C2, Cs, Cs);

    int ty2 = ty * 2;
    int gi0 = by + ty2;          // center rows gi0, gi0+1
    int gj  = bx + tx;

    // chunk window
    int kch = min((gj - 1) / 62, 8);
    int cs = 62 * kch;
    int ce = min(cs + 64, 512);

    const float invS1L = LOG2E / 8145.0625f;   // (19*19/4)^2
    const float invS0L = LOG2E / 126.5625f;    // (5*9/4)^2

    // ---------------- Base: 19x19, two centers ----------------
    float xc0 = sbx[ty2 + 9][tx + 9].x;
    float xc1 = sbx[ty2 + 10][tx + 9].x;
    u64 b10, b11;
    { float a = -2.f * Cs * xc0; PACK2(b10, a, a); }
    { float a = -2.f * Cs * xc1; PACK2(b11, a, a); }
    float cx0 = Cs * xc0 * xc0;
    float cx1 = Cs * xc1 * xc1;

    u64 Lb[10];
    {
        #pragma unroll
        for (int p = 0; p < 10; ++p) {
            float l0 = -1e30f, l1 = -1e30f;
            int dj0 = 2 * p, dj1 = 2 * p + 1;
            int j0 = gj - 9 + dj0, j1 = gj - 9 + dj1;
            if (j0 >= cs && j0 < ce) { int cc = dj0 - 9; l0 = -(float)(cc * cc) * invS1L; }
            if (dj1 < 19 && j1 >= cs && j1 < ce) { int cc = dj1 - 9; l1 = -(float)(cc * cc) * invS1L; }
            PACK2(Lb[p], l0, l1);
        }
    }

    u64 g0 = 0, g1 = 0, g2 = 0, g3 = 0, g4 = 0;      // center0: w, wx, wxx, wy, wxy
    u64 h0 = 0, h1 = 0, h2 = 0, h3 = 0, h4 = 0;      // center1

    #pragma unroll 1
    for (int r = 0; r < 20; ++r) {
        float fd0 = (float)(r - 9), fd1 = (float)(r - 10);
        float lr0 = (r <= 18) ? -fd0 * fd0 * invS1L : -1e30f;
        float lr1 = (r >= 1)  ? -fd1 * fd1 * invS1L : -1e30f;
        float k0 = lr0 + cx0, k1 = lr1 + cx1;
        u64 k02; PACK2(k02, k0, k0);
        u64 k12; PACK2(k12, k1, k1);

        const u64* rbx = (const u64*)&sbx[ty2 + r][tx];
        const u64* rby = (const u64*)&sby[ty2 + r][tx];

        #pragma unroll
        for (int p = 0; p < 10; ++p) {
            u64 vx2 = rbx[2 * p];
            u64 vy2 = rby[2 * p];
            // center 0
            {
                u64 u, a;
                FMA2(u, C2, vx2, b10);
                FMA2(a, u, vx2, Lb[p]);
                ADD2(a, a, k02);
                float a0, a1; UNPACK2(a0, a1, a);
                float w0 = ex2f(a0), w1 = ex2f(a1);
                u64 w; PACK2(w, w0, w1);
                ADD2(g0, g0, w);
                u64 wx; MUL2(wx, w, vx2);
                ADD2(g1, g1, wx);
                FMA2(g2, wx, vx2, g2);
                FMA2(g3, w, vy2, g3);
                FMA2(g4, wx, vy2, g4);
            }
            // center 1
            {
                u64 u, a;
                FMA2(u, C2, vx2, b11);
                FMA2(a, u, vx2, Lb[p]);
                ADD2(a, a, k12);
                float a0, a1; UNPACK2(a0, a1, a);
                float w0 = ex2f(a0), w1 = ex2f(a1);
                u64 w; PACK2(w, w0, w1);
                ADD2(h0, h0, w);
                u64 wx; MUL2(wx, w, vx2);
                ADD2(h1, h1, wx);
                FMA2(h2, wx, vx2, h2);
                FMA2(h3, w, vy2, h3);
                FMA2(h4, wx, vy2, h4);
            }
        }
    }

    float A0, B0, A1, B1;
    {
        float a, b, sw, swx, swxx, swy, swxy;
        UNPACK2(a, b, g0); sw = a + b;
        UNPACK2(a, b, g1); swx = a + b;
        UNPACK2(a, b, g2); swxx = a + b;
        UNPACK2(a, b, g3); swy = a + b;
        UNPACK2(a, b, g4); swxy = a + b;
        float invsw = 1.0f / sw;
        float mx = swx * invsw, my = swy * invsw;
        float var = fmaf(-mx, mx, swxx * invsw);
        float cov = fmaf(-mx, my, swxy * invsw);
        A0 = cov / (var + 1e-6f);
        B0 = fmaf(-A0, mx, my);
    }
    {
        float a, b, sw, swx, swxx, swy, swxy;
        UNPACK2(a, b, h0); sw = a + b;
        UNPACK2(a, b, h1); swx = a + b;
        UNPACK2(a, b, h2); swxx = a + b;
        UNPACK2(a, b, h3); swy = a + b;
        UNPACK2(a, b, h4); swxy = a + b;
        float invsw = 1.0f / sw;
        float mx = swx * invsw, my = swy * invsw;
        float var = fmaf(-mx, mx, swxx * invsw);
        float cov = fmaf(-mx, my, swxy * invsw);
        A1 = cov / (var + 1e-6f);
        B1 = fmaf(-A1, mx, my);
    }

    // ---------------- Detail: 5x9, two centers, shared row loads ----------------
    u64 Ld[5];
    {
        #pragma unroll
        for (int p = 0; p < 5; ++p) {
            float l0 = -1e30f, l1 = -1e30f;
            int dj0 = 2 * p, dj1 = 2 * p + 1;
            int j0 = gj - 4 + dj0, j1 = gj - 4 + dj1;
            if (j0 >= cs && j0 < ce) { int cc = dj0 - 4; l0 = -(float)(cc * cc) * invS0L; }
            if (dj1 < 9 && j1 >= cs && j1 < ce) { int cc = dj1 - 4; l1 = -(float)(cc * cc) * invS0L; }
            PACK2(Ld[p], l0, l1);
        }
    }

    float xd0 = sdx[ty2 + 2][tx + 4].x;
    float xd1 = sdx[ty2 + 3][tx + 4].x;
    u64 bd0p, bd1p;
    { float a = -2.f * Cs * xd0; PACK2(bd0p, a, a); }
    { float a = -2.f * Cs * xd1; PACK2(bd1p, a, a); }
    float cxd0 = Cs * xd0 * xd0;
    float cxd1 = Cs * xd1 * xd1;

    u64 s00 = 0, s01 = 0, s10 = 0, s11 = 0;   // {center}{w|wz}
    #pragma unroll
    for (int r = 0; r < 6; ++r) {
        float fd0 = (float)(r - 2), fd1 = (float)(r - 3);
        float lr0 = (r <= 4) ? -fd0 * fd0 * invS0L : -1e30f;
        float lr1 = (r >= 1) ? -fd1 * fd1 * invS0L : -1e30f;
        float k0 = lr0 + cxd0, k1 = lr1 + cxd1;
        u64 k02; PACK2(k02, k0, k0);
        u64 k12; PACK2(k12, k1, k1);

        const u64* rdx = (const u64*)&sdx[ty2 + r][tx];
        const u64* rdy = (const u64*)&sdy[ty2 + r][tx];
        #pragma unroll
        for (int p = 0; p < 5; ++p) {
            u64 vx2 = rdx[2 * p];
            u64 vy2 = rdy[2 * p];
            {
                u64 u, a;
                FMA2(u, C2, vx2, bd0p);
                FMA2(a, u, vx2, Ld[p]);
                ADD2(a, a, k02);
                float a0, a1; UNPACK2(a0, a1, a);
                float w0 = ex2f(a0), w1 = ex2f(a1);
                u64 w; PACK2(w, w0, w1);
                ADD2(s00, s00, w);
                FMA2(s01, w, vy2, s01);
            }
            {
                u64 u, a;
                FMA2(u, C2, vx2, bd1p);
                FMA2(a, u, vx2, Ld[p]);
                ADD2(a, a, k12);
                float a0, a1; UNPACK2(a0, a1, a);
                float w0 = ex2f(a0), w1 = ex2f(a1);
                u64 w; PACK2(w, w0, w1);
                ADD2(s10, s10, w);
                FMA2(s11, w, vy2, s11);
            }
        }
    }

    float a, b, sw0, sz0, sw1, sz1;
    UNPACK2(a, b, s00); sw0 = a + b;
    UNPACK2(a, b, s01); sz0 = a + b;
    UNPACK2(a, b, s10); sw1 = a + b;
    UNPACK2(a, b, s11); sz1 = a + b;

    out[(gi0 << 9) + gj]       = fmaf(A0, xc0, B0 + xd0 + sz0 / sw0);
    out[((gi0 + 1) << 9) + gj] = fmaf(A1, xc1, B1 + xd1 + sz1 / sw1);
}

extern "C" void kernel_launch(void* const* d_in, const int* in_sizes, int n_in,
                              void* d_out, int out_size) {
    const float* X = (const float*)d_in[0];
    const float* Y = (const float*)d_in[1];
    const float* R = (const float*)d_in[2];
    float* out = (float*)d_out;

    k_pre<<<dim3(16, 64), dim3(32, 8)>>>(X, Y);
    k_main<<<dim3(16, 32), dim3(32, 8)>>>(R, out);
}

// round 12
// speedup vs baseline: 1.1465x; 1.1465x over previous
#include <cuda_runtime.h>

#define MM 512
#define NN 512
#define NPIX (MM*NN)

typedef unsigned long long u64;

__device__ float2 g_base[NPIX];   // {Xb, yb}
__device__ float2 g_det[NPIX];    // {Xd, yd - Xd}
__device__ unsigned g_bmin[1024], g_bmax[1024];

#define LOG2E 1.4426950408889634f

#define FMA2(d,a,b,c) asm("fma.rn.f32x2 %0, %1, %2, %3;" : "=l"(d) : "l"(a), "l"(b), "l"(c))
#define ADD2(d,a,b)   asm("add.rn.f32x2 %0, %1, %2;"     : "=l"(d) : "l"(a), "l"(b))
#define MUL2(d,a,b)   asm("mul.rn.f32x2 %0, %1, %2;"     : "=l"(d) : "l"(a), "l"(b))
#define PACK2(d,lo,hi) asm("mov.b64 %0, {%1, %2};" : "=l"(d) : "f"(lo), "f"(hi))
#define UNPACK2(lo,hi,s) asm("mov.b64 {%0, %1}, %2;" : "=f"(lo), "=f"(hi) : "l"(s))
__device__ __forceinline__ float ex2f(float a) {
    float r; asm("ex2.approx.f32 %0, %1;" : "=f"(r) : "f"(a)); return r;
}

__device__ __forceinline__ unsigned f2key(float f) {
    unsigned u = __float_as_uint(f);
    return (u & 0x80000000u) ? ~u : (u | 0x80000000u);
}
__device__ __forceinline__ float key2f(unsigned k) {
    unsigned u = (k & 0x80000000u) ? (k ^ 0x80000000u) : ~k;
    return __uint_as_float(u);
}

// ---- fused: 9x9 box (zero pad, /81) + detail + per-block y min/max ----
__global__ __launch_bounds__(256) void k_pre(const float* __restrict__ X,
                                             const float* __restrict__ Y) {
    __shared__ float2 raw[16][40];
    __shared__ float2 hs[16][32];
    __shared__ unsigned smn[8], smx[8];

    int tx = threadIdx.x, ty = threadIdx.y;
    int bx = blockIdx.x * 32, by = blockIdx.y * 8;
    int tid = ty * 32 + tx;

    for (int k = tid; k < 16 * 40; k += 256) {
        int r = k / 40, c = k % 40;
        int gi = by + r - 4, gj = bx + c - 4;
        float2 v = make_float2(0.f, 0.f);
        if ((unsigned)gi < 512u && (unsigned)gj < 512u) {
            int idx = (gi << 9) + gj;
            v = make_float2(X[idx], Y[idx]);
        }
        raw[r][c] = v;
    }
    __syncthreads();

    for (int k = tid; k < 16 * 32; k += 256) {
        int r = k >> 5, c = k & 31;
        float sx = 0.f, sy = 0.f;
        #pragma unroll
        for (int d = 0; d < 9; ++d) {
            float2 v = raw[r][c + d];
            sx += v.x; sy += v.y;
        }
        hs[r][c] = make_float2(sx, sy);
    }
    __syncthreads();

    float sx = 0.f, sy = 0.f;
    #pragma unroll
    for (int d = 0; d < 9; ++d) {
        float2 v = hs[ty + d][tx];
        sx += v.x; sy += v.y;
    }
    const float inv81 = 1.0f / 81.0f;
    float xb = sx * inv81, yb = sy * inv81;
    float2 ctr = raw[ty + 4][tx + 4];
    float xd = ctr.x - xb;
    float zd = (ctr.y - yb) - xd;
    int idx = ((by + ty) << 9) + bx + tx;
    g_base[idx] = make_float2(xb, yb);
    g_det[idx]  = make_float2(xd, zd);

    unsigned key = f2key(ctr.y);
    unsigned mn = key, mx = key;
    #pragma unroll
    for (int o = 16; o; o >>= 1) {
        mn = min(mn, __shfl_xor_sync(0xFFFFFFFFu, mn, o));
        mx = max(mx, __shfl_xor_sync(0xFFFFFFFFu, mx, o));
    }
    if ((tid & 31) == 0) { smn[tid >> 5] = mn; smx[tid >> 5] = mx; }
    __syncthreads();
    if (tid == 0) {
        unsigned m = smn[0], M = smx[0];
        #pragma unroll
        for (int w = 1; w < 8; ++w) { m = min(m, smn[w]); M = max(M, smx[w]); }
        int bid = blockIdx.y * 16 + blockIdx.x;
        g_bmin[bid] = m;
        g_bmax[bid] = M;
    }
}

// ================= main bilateral kernel =================
// Tile 32 cols x 8 rows, block 32x4 (128 thr), 2 center rows per thread.
// Overlapping-pair smem: s[r][c] = {v[c], v[c+1]}; stride-2 LDS.64 reads.
// 3-op exponent: a = (C*v + b1)*v + Lb[p] + (lr + C*x^2), b1 = -2Cx.
// Sentinel rows x=1e19 -> w=0. 102-reg budget (5 blocks/SM) for sw pipelining.
#define TROW 26      // 8 + 2*9
#define TCOL 50      // 32 + 2*9
#define DROW 12      // 8 + 2*2
#define DCOL 40      // 32 + 2*4

__global__ __launch_bounds__(128, 5) void k_main(const float* __restrict__ R,
                                                 float* __restrict__ out) {
    __shared__ float2 sbx[TROW][TCOL];
    __shared__ float2 sby[TROW][TCOL];
    __shared__ float2 sdx[DROW][DCOL];
    __shared__ float2 sdy[DROW][DCOL];
    __shared__ unsigned smn[4], smx[4];

    int tx = threadIdx.x, ty = threadIdx.y;
    int bx = blockIdx.x * 32, by = blockIdx.y * 8;
    int tid = ty * 32 + tx;

    // global min/max reduction from k_pre partials
    {
        unsigned mn = 0xFFFFFFFFu, mx = 0u;
        #pragma unroll
        for (int i = 0; i < 8; ++i) {
            int k = tid + 128 * i;
            mn = min(mn, g_bmin[k]);
            mx = max(mx, g_bmax[k]);
        }
        #pragma unroll
        for (int o = 16; o; o >>= 1) {
            mn = min(mn, __shfl_xor_sync(0xFFFFFFFFu, mn, o));
            mx = max(mx, __shfl_xor_sync(0xFFFFFFFFu, mx, o));
        }
        if ((tid & 31) == 0) { smn[tid >> 5] = mn; smx[tid >> 5] = mx; }
    }

    // Zero the never-filled last .y slots (finite; col mask forces w=0)
    if (tid < TROW) {
        sbx[tid][TCOL - 1].y = 0.f;
        sby[tid][TCOL - 1].y = 0.f;
    }
    if (tid < DROW) {
        sdx[tid][DCOL - 1].y = 0.f;
        sdy[tid][DCOL - 1].y = 0.f;
    }

    // Tile fill; out-of-range rows get sentinel x=1e19 (=> w=0), y=0
    for (int k = tid; k < TROW * TCOL; k += 128) {
        int r = k / TCOL, c = k % TCOL;
        int gi = by + r - 9;
        int gj = min(max(bx + c - 9, 0), 511);
        float vx = 1e19f, vy = 0.f;
        if ((unsigned)gi < 512u) {
            float2 v = g_base[(gi << 9) + gj];
            vx = v.x; vy = v.y;
        }
        sbx[r][c].x = vx;
        sby[r][c].x = vy;
        if (c > 0) { sbx[r][c - 1].y = vx; sby[r][c - 1].y = vy; }
    }
    for (int k = tid; k < DROW * DCOL; k += 128) {
        int r = k / DCOL, c = k % DCOL;
        int gi = by + r - 2;
        int gj = min(max(bx + c - 4, 0), 511);
        float vx = 1e19f, vy = 0.f;
        if ((unsigned)gi < 512u) {
            float2 v = g_det[(gi << 9) + gj];
            vx = v.x; vy = v.y;
        }
        sdx[r][c].x = vx;
        sdy[r][c].x = vy;
        if (c > 0) { sdx[r][c - 1].y = vx; sdy[r][c - 1].y = vy; }
    }
    __syncthreads();

    float Cs;
    {
        unsigned m = min(min(smn[0], smn[1]), min(smn[2], smn[3]));
        unsigned M = max(max(smx[0], smx[1]), max(smx[2], smx[3]));
        float sigma = R[0] * (key2f(M) - key2f(m));
        float h = sigma * 0.5f;
        Cs = -LOG2E / (h * h);
    }
    u64 C2; PACK2(C2, Cs, Cs);

    int ty2 = ty * 2;
    int gi0 = by + ty2;          // center rows gi0, gi0+1
    int gj  = bx + tx;

    // chunk window
    int kch = min((gj - 1) / 62, 8);
    int cs = 62 * kch;
    int ce = min(cs + 64, 512);

    const float invS1L = LOG2E / 8145.0625f;   // (19*19/4)^2
    const float invS0L = LOG2E / 126.5625f;    // (5*9/4)^2

    // ---------------- Base: 19x19, two centers ----------------
    float xc0 = sbx[ty2 + 9][tx + 9].x;
    float xc1 = sbx[ty2 + 10][tx + 9].x;
    u64 b10, b11;
    { float a = -2.f * Cs * xc0; PACK2(b10, a, a); }
    { float a = -2.f * Cs * xc1; PACK2(b11, a, a); }
    float cx0 = Cs * xc0 * xc0;
    float cx1 = Cs * xc1 * xc1;

    u64 Lb[10];
    {
        #pragma unroll
        for (int p = 0; p < 10; ++p) {
            float l0 = -1e30f, l1 = -1e30f;
            int dj0 = 2 * p, dj1 = 2 * p + 1;
            int j0 = gj - 9 + dj0, j1 = gj - 9 + dj1;
            if (j0 >= cs && j0 < ce) { int cc = dj0 - 9; l0 = -(float)(cc * cc) * invS1L; }
            if (dj1 < 19 && j1 >= cs && j1 < ce) { int cc = dj1 - 9; l1 = -(float)(cc * cc) * invS1L; }
            PACK2(Lb[p], l0, l1);
        }
    }

    u64 g0 = 0, g1 = 0, g2 = 0, g3 = 0, g4 = 0;      // center0: w, wx, wxx, wy, wxy
    u64 h0 = 0, h1 = 0, h2 = 0, h3 = 0, h4 = 0;      // center1

    #pragma unroll 1
    for (int r = 0; r < 20; ++r) {
        float fd0 = (float)(r - 9), fd1 = (float)(r - 10);
        float lr0 = (r <= 18) ? -fd0 * fd0 * invS1L : -1e30f;
        float lr1 = (r >= 1)  ? -fd1 * fd1 * invS1L : -1e30f;
        float k0 = lr0 + cx0, k1 = lr1 + cx1;
        u64 k02; PACK2(k02, k0, k0);
        u64 k12; PACK2(k12, k1, k1);

        const u64* rbx = (const u64*)&sbx[ty2 + r][tx];
        const u64* rby = (const u64*)&sby[ty2 + r][tx];

        #pragma unroll
        for (int p = 0; p < 10; ++p) {
            u64 vx2 = rbx[2 * p];
            u64 vy2 = rby[2 * p];
            // center 0
            {
                u64 u, a;
                FMA2(u, C2, vx2, b10);
                FMA2(a, u, vx2, Lb[p]);
                ADD2(a, a, k02);
                float a0, a1; UNPACK2(a0, a1, a);
                float w0 = ex2f(a0), w1 = ex2f(a1);
                u64 w; PACK2(w, w0, w1);
                ADD2(g0, g0, w);
                u64 wx; MUL2(wx, w, vx2);
                ADD2(g1, g1, wx);
                FMA2(g2, wx, vx2, g2);
                FMA2(g3, w, vy2, g3);
                FMA2(g4, wx, vy2, g4);
            }
            // center 1
            {
                u64 u, a;
                FMA2(u, C2, vx2, b11);
                FMA2(a, u, vx2, Lb[p]);
                ADD2(a, a, k12);
                float a0, a1; UNPACK2(a0, a1, a);
                float w0 = ex2f(a0), w1 = ex2f(a1);
                u64 w; PACK2(w, w0, w1);
                ADD2(h0, h0, w);
                u64 wx; MUL2(wx, w, vx2);
                ADD2(h1, h1, wx);
                FMA2(h2, wx, vx2, h2);
                FMA2(h3, w, vy2, h3);
                FMA2(h4, wx, vy2, h4);
            }
        }
    }

    float A0, B0, A1, B1;
    {
        float a, b, sw, swx, swxx, swy, swxy;
        UNPACK2(a, b, g0); sw = a + b;
        UNPACK2(a, b, g1); swx = a + b;
        UNPACK2(a, b, g2); swxx = a + b;
        UNPACK2(a, b, g3); swy = a + b;
        UNPACK2(a, b, g4); swxy = a + b;
        float invsw = 1.0f / sw;
        float mx = swx * invsw, my = swy * invsw;
        float var = fmaf(-mx, mx, swxx * invsw);
        float cov = fmaf(-mx, my, swxy * invsw);
        A0 = cov / (var + 1e-6f);
        B0 = fmaf(-A0, mx, my);
    }
    {
        float a, b, sw, swx, swxx, swy, swxy;
        UNPACK2(a, b, h0); sw = a + b;
        UNPACK2(a, b, h1); swx = a + b;
        UNPACK2(a, b, h2); swxx = a + b;
        UNPACK2(a, b, h3); swy = a + b;
        UNPACK2(a, b, h4); swxy = a + b;
        float invsw = 1.0f / sw;
        float mx = swx * invsw, my = swy * invsw;
        float var = fmaf(-mx, mx, swxx * invsw);
        float cov = fmaf(-mx, my, swxy * invsw);
        A1 = cov / (var + 1e-6f);
        B1 = fmaf(-A1, mx, my);
    }

    // ---------------- Detail: 5x9, two centers, shared row loads ----------------
    u64 Ld[5];
    {
        #pragma unroll
        for (int p = 0; p < 5; ++p) {
            float l0 = -1e30f, l1 = -1e30f;
            int dj0 = 2 * p, dj1 = 2 * p + 1;
            int j0 = gj - 4 + dj0, j1 = gj - 4 + dj1;
            if (j0 >= cs && j0 < ce) { int cc = dj0 - 4; l0 = -(float)(cc * cc) * invS0L; }
            if (dj1 < 9 && j1 >= cs && j1 < ce) { int cc = dj1 - 4; l1 = -(float)(cc * cc) * invS0L; }
            PACK2(Ld[p], l0, l1);
        }
    }

    float xd0 = sdx[ty2 + 2][tx + 4].x;
    float xd1 = sdx[ty2 + 3][tx + 4].x;
    u64 bd0p, bd1p;
    { float a = -2.f * Cs * xd0; PACK2(bd0p, a, a); }
    { float a = -2.f * Cs * xd1; PACK2(bd1p, a, a); }
    float cxd0 = Cs * xd0 * xd0;
    float cxd1 = Cs * xd1 * xd1;

    u64 s00 = 0, s01 = 0, s10 = 0, s11 = 0;   // {center}{w|wz}
    #pragma unroll
    for (int r = 0; r < 6; ++r) {
        float fd0 = (float)(r - 2), fd1 = (float)(r - 3);
        float lr0 = (r <= 4) ? -fd0 * fd0 * invS0L : -1e30f;
        float lr1 = (r >= 1) ? -fd1 * fd1 * invS0L : -1e30f;
        float k0 = lr0 + cxd0, k1 = lr1 + cxd1;
        u64 k02; PACK2(k02, k0, k0);
        u64 k12; PACK2(k12, k1, k1);

        const u64* rdx = (const u64*)&sdx[ty2 + r][tx];
        const u64* rdy = (const u64*)&sdy[ty2 + r][tx];
        #pragma unroll
        for (int p = 0; p < 5; ++p) {
            u64 vx2 = rdx[2 * p];
            u64 vy2 = rdy[2 * p];
            {
                u64 u, a;
                FMA2(u, C2, vx2, bd0p);
                FMA2(a, u, vx2, Ld[p]);
                ADD2(a, a, k02);
                float a0, a1; UNPACK2(a0, a1, a);
                float w0 = ex2f(a0), w1 = ex2f(a1);
                u64 w; PACK2(w, w0, w1);
                ADD2(s00, s00, w);
                FMA2(s01, w, vy2, s01);
            }
            {
                u64 u, a;
                FMA2(u, C2, vx2, bd1p);
                FMA2(a, u, vx2, Ld[p]);
                ADD2(a, a, k12);
                float a0, a1; UNPACK2(a0, a1, a);
                float w0 = ex2f(a0), w1 = ex2f(a1);
                u64 w; PACK2(w, w0, w1);
                ADD2(s10, s10, w);
                FMA2(s11, w, vy2, s11);
            }
        }
    }

    float a, b, sw0, sz0, sw1, sz1;
    UNPACK2(a, b, s00); sw0 = a + b;
    UNPACK2(a, b, s01); sz0 = a + b;
    UNPACK2(a, b, s10); sw1 = a + b;
    UNPACK2(a, b, s11); sz1 = a + b;

    out[(gi0 << 9) + gj]       = fmaf(A0, xc0, B0 + xd0 + sz0 / sw0);
    out[((gi0 + 1) << 9) + gj] = fmaf(A1, xc1, B1 + xd1 + sz1 / sw1);
}

extern "C" void kernel_launch(void* const* d_in, const int* in_sizes, int n_in,
                              void* d_out, int out_size) {
    const float* X = (const float*)d_in[0];
    const float* Y = (const float*)d_in[1];
    const float* R = (const float*)d_in[2];
    float* out = (float*)d_out;

    k_pre<<<dim3(16, 64), dim3(32, 8)>>>(X, Y);
    k_main<<<dim3(16, 64), dim3(32, 4)>>>(R, out);
}

// round 13
// speedup vs baseline: 1.1539x; 1.0065x over previous
#include <cuda_runtime.h>

#define MM 512
#define NN 512
#define NPIX (MM*NN)

typedef unsigned long long u64;

__device__ float2 g_base[NPIX];   // {Xb, yb}
__device__ float2 g_det[NPIX];    // {Xd, yd - Xd}
__device__ unsigned g_bmin[1024], g_bmax[1024];

#define LOG2E 1.4426950408889634f

#define FMA2(d,a,b,c) asm("fma.rn.f32x2 %0, %1, %2, %3;" : "=l"(d) : "l"(a), "l"(b), "l"(c))
#define ADD2(d,a,b)   asm("add.rn.f32x2 %0, %1, %2;"     : "=l"(d) : "l"(a), "l"(b))
#define MUL2(d,a,b)   asm("mul.rn.f32x2 %0, %1, %2;"     : "=l"(d) : "l"(a), "l"(b))
#define PACK2(d,lo,hi) asm("mov.b64 %0, {%1, %2};" : "=l"(d) : "f"(lo), "f"(hi))
#define UNPACK2(lo,hi,s) asm("mov.b64 {%0, %1}, %2;" : "=f"(lo), "=f"(hi) : "l"(s))
__device__ __forceinline__ float ex2f(float a) {
    float r; asm("ex2.approx.f32 %0, %1;" : "=f"(r) : "f"(a)); return r;
}

__device__ __forceinline__ unsigned f2key(float f) {
    unsigned u = __float_as_uint(f);
    return (u & 0x80000000u) ? ~u : (u | 0x80000000u);
}
__device__ __forceinline__ float key2f(unsigned k) {
    unsigned u = (k & 0x80000000u) ? (k ^ 0x80000000u) : ~k;
    return __uint_as_float(u);
}

// ---- fused: 9x9 box (zero pad, /81) + detail + per-block y min/max ----
__global__ __launch_bounds__(256) void k_pre(const float* __restrict__ X,
                                             const float* __restrict__ Y) {
    __shared__ float2 raw[16][40];
    __shared__ float2 hs[16][32];
    __shared__ unsigned smn[8], smx[8];

    int tx = threadIdx.x, ty = threadIdx.y;
    int bx = blockIdx.x * 32, by = blockIdx.y * 8;
    int tid = ty * 32 + tx;

    for (int k = tid; k < 16 * 40; k += 256) {
        int r = k / 40, c = k % 40;
        int gi = by + r - 4, gj = bx + c - 4;
        float2 v = make_float2(0.f, 0.f);
        if ((unsigned)gi < 512u && (unsigned)gj < 512u) {
            int idx = (gi << 9) + gj;
            v = make_float2(X[idx], Y[idx]);
        }
        raw[r][c] = v;
    }
    __syncthreads();

    for (int k = tid; k < 16 * 32; k += 256) {
        int r = k >> 5, c = k & 31;
        float sx = 0.f, sy = 0.f;
        #pragma unroll
        for (int d = 0; d < 9; ++d) {
            float2 v = raw[r][c + d];
            sx += v.x; sy += v.y;
        }
        hs[r][c] = make_float2(sx, sy);
    }
    __syncthreads();

    float sx = 0.f, sy = 0.f;
    #pragma unroll
    for (int d = 0; d < 9; ++d) {
        float2 v = hs[ty + d][tx];
        sx += v.x; sy += v.y;
    }
    const float inv81 = 1.0f / 81.0f;
    float xb = sx * inv81, yb = sy * inv81;
    float2 ctr = raw[ty + 4][tx + 4];
    float xd = ctr.x - xb;
    float zd = (ctr.y - yb) - xd;
    int idx = ((by + ty) << 9) + bx + tx;
    g_base[idx] = make_float2(xb, yb);
    g_det[idx]  = make_float2(xd, zd);

    unsigned key = f2key(ctr.y);
    unsigned mn = key, mx = key;
    #pragma unroll
    for (int o = 16; o; o >>= 1) {
        mn = min(mn, __shfl_xor_sync(0xFFFFFFFFu, mn, o));
        mx = max(mx, __shfl_xor_sync(0xFFFFFFFFu, mx, o));
    }
    if ((tid & 31) == 0) { smn[tid >> 5] = mn; smx[tid >> 5] = mx; }
    __syncthreads();
    if (tid == 0) {
        unsigned m = smn[0], M = smx[0];
        #pragma unroll
        for (int w = 1; w < 8; ++w) { m = min(m, smn[w]); M = max(M, smx[w]); }
        int bid = blockIdx.y * 16 + blockIdx.x;
        g_bmin[bid] = m;
        g_bmax[bid] = M;
    }
}

// ================= main bilateral kernel =================
// Tile 32 cols x 8 rows, block 32x4 (128 thr), 2 center rows per thread.
// Overlapping-pair smem: s[r][c] = {v[c], v[c+1]}; stride-2 LDS.64 reads.
// 3-op exponent: a = (C*v + b1)*v + Lb[p] + (lr + C*x^2), b1 = -2Cx.
// Sentinel rows x=1e19 -> w=0. 128-reg budget (4 blocks/SM) for sw pipelining.
#define TROW 26      // 8 + 2*9
#define TCOL 50      // 32 + 2*9
#define DROW 12      // 8 + 2*2
#define DCOL 40      // 32 + 2*4

__global__ __launch_bounds__(128, 4) void k_main(const float* __restrict__ R,
                                                 float* __restrict__ out) {
    __shared__ float2 sbx[TROW][TCOL];
    __shared__ float2 sby[TROW][TCOL];
    __shared__ float2 sdx[DROW][DCOL];
    __shared__ float2 sdy[DROW][DCOL];
    __shared__ unsigned smn[4], smx[4];

    int tx = threadIdx.x, ty = threadIdx.y;
    int bx = blockIdx.x * 32, by = blockIdx.y * 8;
    int tid = ty * 32 + tx;

    // global min/max reduction from k_pre partials
    {
        unsigned mn = 0xFFFFFFFFu, mx = 0u;
        #pragma unroll
        for (int i = 0; i < 8; ++i) {
            int k = tid + 128 * i;
            mn = min(mn, g_bmin[k]);
            mx = max(mx, g_bmax[k]);
        }
        #pragma unroll
        for (int o = 16; o; o >>= 1) {
            mn = min(mn, __shfl_xor_sync(0xFFFFFFFFu, mn, o));
            mx = max(mx, __shfl_xor_sync(0xFFFFFFFFu, mx, o));
        }
        if ((tid & 31) == 0) { smn[tid >> 5] = mn; smx[tid >> 5] = mx; }
    }

    // Zero the never-filled last .y slots (finite; col mask forces w=0)
    if (tid < TROW) {
        sbx[tid][TCOL - 1].y = 0.f;
        sby[tid][TCOL - 1].y = 0.f;
    }
    if (tid < DROW) {
        sdx[tid][DCOL - 1].y = 0.f;
        sdy[tid][DCOL - 1].y = 0.f;
    }

    // Tile fill; out-of-range rows get sentinel x=1e19 (=> w=0), y=0
    for (int k = tid; k < TROW * TCOL; k += 128) {
        int r = k / TCOL, c = k % TCOL;
        int gi = by + r - 9;
        int gj = min(max(bx + c - 9, 0), 511);
        float vx = 1e19f, vy = 0.f;
        if ((unsigned)gi < 512u) {
            float2 v = g_base[(gi << 9) + gj];
            vx = v.x; vy = v.y;
        }
        sbx[r][c].x = vx;
        sby[r][c].x = vy;
        if (c > 0) { sbx[r][c - 1].y = vx; sby[r][c - 1].y = vy; }
    }
    for (int k = tid; k < DROW * DCOL; k += 128) {
        int r = k / DCOL, c = k % DCOL;
        int gi = by + r - 2;
        int gj = min(max(bx + c - 4, 0), 511);
        float vx = 1e19f, vy = 0.f;
        if ((unsigned)gi < 512u) {
            float2 v = g_det[(gi << 9) + gj];
            vx = v.x; vy = v.y;
        }
        sdx[r][c].x = vx;
        sdy[r][c].x = vy;
        if (c > 0) { sdx[r][c - 1].y = vx; sdy[r][c - 1].y = vy; }
    }
    __syncthreads();

    float Cs;
    {
        unsigned m = min(min(smn[0], smn[1]), min(smn[2], smn[3]));
        unsigned M = max(max(smx[0], smx[1]), max(smx[2], smx[3]));
        float sigma = R[0] * (key2f(M) - key2f(m));
        float h = sigma * 0.5f;
        Cs = -LOG2E / (h * h);
    }
    u64 C2; PACK2(C2, Cs, Cs);

    int ty2 = ty * 2;
    int gi0 = by + ty2;          // center rows gi0, gi0+1
    int gj  = bx + tx;

    // chunk window
    int kch = min((gj - 1) / 62, 8);
    int cs = 62 * kch;
    int ce = min(cs + 64, 512);

    const float invS1L = LOG2E / 8145.0625f;   // (19*19/4)^2
    const float invS0L = LOG2E / 126.5625f;    // (5*9/4)^2

    // ---------------- Base: 19x19, two centers ----------------
    float xc0 = sbx[ty2 + 9][tx + 9].x;
    float xc1 = sbx[ty2 + 10][tx + 9].x;
    u64 b10, b11;
    { float a = -2.f * Cs * xc0; PACK2(b10, a, a); }
    { float a = -2.f * Cs * xc1; PACK2(b11, a, a); }
    float cx0 = Cs * xc0 * xc0;
    float cx1 = Cs * xc1 * xc1;

    u64 Lb[10];
    {
        #pragma unroll
        for (int p = 0; p < 10; ++p) {
            float l0 = -1e30f, l1 = -1e30f;
            int dj0 = 2 * p, dj1 = 2 * p + 1;
            int j0 = gj - 9 + dj0, j1 = gj - 9 + dj1;
            if (j0 >= cs && j0 < ce) { int cc = dj0 - 9; l0 = -(float)(cc * cc) * invS1L; }
            if (dj1 < 19 && j1 >= cs && j1 < ce) { int cc = dj1 - 9; l1 = -(float)(cc * cc) * invS1L; }
            PACK2(Lb[p], l0, l1);
        }
    }

    u64 g0 = 0, g1 = 0, g2 = 0, g3 = 0, g4 = 0;      // center0: w, wx, wxx, wy, wxy
    u64 h0 = 0, h1 = 0, h2 = 0, h3 = 0, h4 = 0;      // center1

    #pragma unroll 1
    for (int r = 0; r < 20; ++r) {
        float fd0 = (float)(r - 9), fd1 = (float)(r - 10);
        float lr0 = (r <= 18) ? -fd0 * fd0 * invS1L : -1e30f;
        float lr1 = (r >= 1)  ? -fd1 * fd1 * invS1L : -1e30f;
        float k0 = lr0 + cx0, k1 = lr1 + cx1;
        u64 k02; PACK2(k02, k0, k0);
        u64 k12; PACK2(k12, k1, k1);

        const u64* rbx = (const u64*)&sbx[ty2 + r][tx];
        const u64* rby = (const u64*)&sby[ty2 + r][tx];

        #pragma unroll
        for (int p = 0; p < 10; ++p) {
            u64 vx2 = rbx[2 * p];
            u64 vy2 = rby[2 * p];
            // center 0
            {
                u64 u, a;
                FMA2(u, C2, vx2, b10);
                FMA2(a, u, vx2, Lb[p]);
                ADD2(a, a, k02);
                float a0, a1; UNPACK2(a0, a1, a);
                float w0 = ex2f(a0), w1 = ex2f(a1);
                u64 w; PACK2(w, w0, w1);
                ADD2(g0, g0, w);
                u64 wx; MUL2(wx, w, vx2);
                ADD2(g1, g1, wx);
                FMA2(g2, wx, vx2, g2);
                FMA2(g3, w, vy2, g3);
                FMA2(g4, wx, vy2, g4);
            }
            // center 1
            {
                u64 u, a;
                FMA2(u, C2, vx2, b11);
                FMA2(a, u, vx2, Lb[p]);
                ADD2(a, a, k12);
                float a0, a1; UNPACK2(a0, a1, a);
                float w0 = ex2f(a0), w1 = ex2f(a1);
                u64 w; PACK2(w, w0, w1);
                ADD2(h0, h0, w);
                u64 wx; MUL2(wx, w, vx2);
                ADD2(h1, h1, wx);
                FMA2(h2, wx, vx2, h2);
                FMA2(h3, w, vy2, h3);
                FMA2(h4, wx, vy2, h4);
            }
        }
    }

    float A0, B0, A1, B1;
    {
        float a, b, sw, swx, swxx, swy, swxy;
        UNPACK2(a, b, g0); sw = a + b;
        UNPACK2(a, b, g1); swx = a + b;
        UNPACK2(a, b, g2); swxx = a + b;
        UNPACK2(a, b, g3); swy = a + b;
        UNPACK2(a, b, g4); swxy = a + b;
        float invsw = 1.0f / sw;
        float mx = swx * invsw, my = swy * invsw;
        float var = fmaf(-mx, mx, swxx * invsw);
        float cov = fmaf(-mx, my, swxy * invsw);
        A0 = cov / (var + 1e-6f);
        B0 = fmaf(-A0, mx, my);
    }
    {
        float a, b, sw, swx, swxx, swy, swxy;
        UNPACK2(a, b, h0); sw = a + b;
        UNPACK2(a, b, h1); swx = a + b;
        UNPACK2(a, b, h2); swxx = a + b;
        UNPACK2(a, b, h3); swy = a + b;
        UNPACK2(a, b, h4); swxy = a + b;
        float invsw = 1.0f / sw;
        float mx = swx * invsw, my = swy * invsw;
        float var = fmaf(-mx, mx, swxx * invsw);
        float cov = fmaf(-mx, my, swxy * invsw);
        A1 = cov / (var + 1e-6f);
        B1 = fmaf(-A1, mx, my);
    }

    // ---------------- Detail: 5x9, two centers, shared row loads ----------------
    u64 Ld[5];
    {
        #pragma unroll
        for (int p = 0; p < 5; ++p) {
            float l0 = -1e30f, l1 = -1e30f;
            int dj0 = 2 * p, dj1 = 2 * p + 1;
            int j0 = gj - 4 + dj0, j1 = gj - 4 + dj1;
            if (j0 >= cs && j0 < ce) { int cc = dj0 - 4; l0 = -(float)(cc * cc) * invS0L; }
            if (dj1 < 9 && j1 >= cs && j1 < ce) { int cc = dj1 - 4; l1 = -(float)(cc * cc) * invS0L; }
            PACK2(Ld[p], l0, l1);
        }
    }

    float xd0 = sdx[ty2 + 2][tx + 4].x;
    float xd1 = sdx[ty2 + 3][tx + 4].x;
    u64 bd0p, bd1p;
    { float a = -2.f * Cs * xd0; PACK2(bd0p, a, a); }
    { float a = -2.f * Cs * xd1; PACK2(bd1p, a, a); }
    float cxd0 = Cs * xd0 * xd0;
    float cxd1 = Cs * xd1 * xd1;

    u64 s00 = 0, s01 = 0, s10 = 0, s11 = 0;   // {center}{w|wz}
    #pragma unroll
    for (int r = 0; r < 6; ++r) {
        float fd0 = (float)(r - 2), fd1 = (float)(r - 3);
        float lr0 = (r <= 4) ? -fd0 * fd0 * invS0L : -1e30f;
        float lr1 = (r >= 1) ? -fd1 * fd1 * invS0L : -1e30f;
        float k0 = lr0 + cxd0, k1 = lr1 + cxd1;
        u64 k02; PACK2(k02, k0, k0);
        u64 k12; PACK2(k12, k1, k1);

        const u64* rdx = (const u64*)&sdx[ty2 + r][tx];
        const u64* rdy = (const u64*)&sdy[ty2 + r][tx];
        #pragma unroll
        for (int p = 0; p < 5; ++p) {
            u64 vx2 = rdx[2 * p];
            u64 vy2 = rdy[2 * p];
            {
                u64 u, a;
                FMA2(u, C2, vx2, bd0p);
                FMA2(a, u, vx2, Ld[p]);
                ADD2(a, a, k02);
                float a0, a1; UNPACK2(a0, a1, a);
                float w0 = ex2f(a0), w1 = ex2f(a1);
                u64 w; PACK2(w, w0, w1);
                ADD2(s00, s00, w);
                FMA2(s01, w, vy2, s01);
            }
            {
                u64 u, a;
                FMA2(u, C2, vx2, bd1p);
                FMA2(a, u, vx2, Ld[p]);
                ADD2(a, a, k12);
                float a0, a1; UNPACK2(a0, a1, a);
                float w0 = ex2f(a0), w1 = ex2f(a1);
                u64 w; PACK2(w, w0, w1);
                ADD2(s10, s10, w);
                FMA2(s11, w, vy2, s11);
            }
        }
    }

    float a, b, sw0, sz0, sw1, sz1;
    UNPACK2(a, b, s00); sw0 = a + b;
    UNPACK2(a, b, s01); sz0 = a + b;
    UNPACK2(a, b, s10); sw1 = a + b;
    UNPACK2(a, b, s11); sz1 = a + b;

    out[(gi0 << 9) + gj]       = fmaf(A0, xc0, B0 + xd0 + sz0 / sw0);
    out[((gi0 + 1) << 9) + gj] = fmaf(A1, xc1, B1 + xd1 + sz1 / sw1);
}

extern "C" void kernel_launch(void* const* d_in, const int* in_sizes, int n_in,
                              void* d_out, int out_size) {
    const float* X = (const float*)d_in[0];
    const float* Y = (const float*)d_in[1];
    const float* R = (const float*)d_in[2];
    float* out = (float*)d_out;

    k_pre<<<dim3(16, 64), dim3(32, 8)>>>(X, Y);
    k_main<<<dim3(16, 64), dim3(32, 4)>>>(R, out);
}

// round 15
// speedup vs baseline: 1.2377x; 1.0726x over previous
#include <cuda_runtime.h>

#define MM 512
#define NN 512
#define NPIX (MM*NN)

typedef unsigned long long u64;

__device__ float2 g_base[NPIX];   // {Xb, yb}
__device__ float2 g_det[NPIX];    // {Xd, yd - Xd}
__device__ unsigned g_bmin[1024], g_bmax[1024];

#define LOG2E 1.4426950408889634f

#define FMA2(d,a,b,c) asm("fma.rn.f32x2 %0, %1, %2, %3;" : "=l"(d) : "l"(a), "l"(b), "l"(c))
#define ADD2(d,a,b)   asm("add.rn.f32x2 %0, %1, %2;"     : "=l"(d) : "l"(a), "l"(b))
#define MUL2(d,a,b)   asm("mul.rn.f32x2 %0, %1, %2;"     : "=l"(d) : "l"(a), "l"(b))
#define PACK2(d,lo,hi) asm("mov.b64 %0, {%1, %2};" : "=l"(d) : "f"(lo), "f"(hi))
#define UNPACK2(lo,hi,s) asm("mov.b64 {%0, %1}, %2;" : "=f"(lo), "=f"(hi) : "l"(s))

// Fused pairwise exp2: unpack+ex2+ex2+pack in ONE asm block so ptxas can
// coalesce the register pairs (source dead after) and drop the MOVs.
#define EXP2PAIR(w, a) asm("{\n\t" \
    ".reg .f32 elo, ehi;\n\t" \
    "mov.b64 {elo, ehi}, %1;\n\t" \
    "ex2.approx.f32 elo, elo;\n\t" \
    "ex2.approx.f32 ehi, ehi;\n\t" \
    "mov.b64 %0, {elo, ehi};\n\t" \
    "}" : "=l"(w) : "l"(a))

// 5-moment accumulate from packed weight w
#define ACC5(G0,G1,G2,G3,G4,w,vx2,vy2) do { \
    u64 wx_; ADD2(G0, G0, w); MUL2(wx_, w, vx2); ADD2(G1, G1, wx_); \
    FMA2(G2, wx_, vx2, G2); FMA2(G3, w, vy2, G3); FMA2(G4, wx_, vy2, G4); } while (0)

__device__ __forceinline__ unsigned f2key(float f) {
    unsigned u = __float_as_uint(f);
    return (u & 0x80000000u) ? ~u : (u | 0x80000000u);
}
__device__ __forceinline__ float key2f(unsigned k) {
    unsigned u = (k & 0x80000000u) ? (k ^ 0x80000000u) : ~k;
    return __uint_as_float(u);
}

// ---- fused: 9x9 box (zero pad, /81) + detail + per-block y min/max ----
__global__ __launch_bounds__(256) void k_pre(const float* __restrict__ X,
                                             const float* __restrict__ Y) {
    __shared__ float2 raw[16][40];
    __shared__ float2 hs[16][32];
    __shared__ unsigned smn[8], smx[8];

    int tx = threadIdx.x, ty = threadIdx.y;
    int bx = blockIdx.x * 32, by = blockIdx.y * 8;
    int tid = ty * 32 + tx;

    for (int k = tid; k < 16 * 40; k += 256) {
        int r = k / 40, c = k % 40;
        int gi = by + r - 4, gj = bx + c - 4;
        float2 v = make_float2(0.f, 0.f);
        if ((unsigned)gi < 512u && (unsigned)gj < 512u) {
            int idx = (gi << 9) + gj;
            v = make_float2(X[idx], Y[idx]);
        }
        raw[r][c] = v;
    }
    __syncthreads();

    for (int k = tid; k < 16 * 32; k += 256) {
        int r = k >> 5, c = k & 31;
        float sx = 0.f, sy = 0.f;
        #pragma unroll
        for (int d = 0; d < 9; ++d) {
            float2 v = raw[r][c + d];
            sx += v.x; sy += v.y;
        }
        hs[r][c] = make_float2(sx, sy);
    }
    __syncthreads();

    float sx = 0.f, sy = 0.f;
    #pragma unroll
    for (int d = 0; d < 9; ++d) {
        float2 v = hs[ty + d][tx];
        sx += v.x; sy += v.y;
    }
    const float inv81 = 1.0f / 81.0f;
    float xb = sx * inv81, yb = sy * inv81;
    float2 ctr = raw[ty + 4][tx + 4];
    float xd = ctr.x - xb;
    float zd = (ctr.y - yb) - xd;
    int idx = ((by + ty) << 9) + bx + tx;
    g_base[idx] = make_float2(xb, yb);
    g_det[idx]  = make_float2(xd, zd);

    unsigned key = f2key(ctr.y);
    unsigned mn = key, mx = key;
    #pragma unroll
    for (int o = 16; o; o >>= 1) {
        mn = min(mn, __shfl_xor_sync(0xFFFFFFFFu, mn, o));
        mx = max(mx, __shfl_xor_sync(0xFFFFFFFFu, mx, o));
    }
    if ((tid & 31) == 0) { smn[tid >> 5] = mn; smx[tid >> 5] = mx; }
    __syncthreads();
    if (tid == 0) {
        unsigned m = smn[0], M = smx[0];
        #pragma unroll
        for (int w = 1; w < 8; ++w) { m = min(m, smn[w]); M = max(M, smx[w]); }
        int bid = blockIdx.y * 16 + blockIdx.x;
        g_bmin[bid] = m;
        g_bmax[bid] = M;
    }
}

// ================= main bilateral kernel =================
// Tile 32x8, block 32x4, 2 center rows/thread. Overlapping-pair smem,
// stride-2 LDS.64. Center0 exponent in 3 packed ops; center1 via delta
// a1 = a0 + (db*v + dk) on interior rows (2 ops). Boundary rows peeled.
#define TROW 26      // 8 + 2*9
#define TCOL 50      // 32 + 2*9
#define DROW 12      // 8 + 2*2
#define DCOL 40      // 32 + 2*4

__global__ __launch_bounds__(128, 4) void k_main(const float* __restrict__ R,
                                                 float* __restrict__ out) {
    __shared__ float2 sbx[TROW][TCOL];
    __shared__ float2 sby[TROW][TCOL];
    __shared__ float2 sdx[DROW][DCOL];
    __shared__ float2 sdy[DROW][DCOL];
    __shared__ unsigned smn[4], smx[4];

    int tx = threadIdx.x, ty = threadIdx.y;
    int bx = blockIdx.x * 32, by = blockIdx.y * 8;
    int tid = ty * 32 + tx;

    // global min/max reduction from k_pre partials
    {
        unsigned mn = 0xFFFFFFFFu, mx = 0u;
        #pragma unroll
        for (int i = 0; i < 8; ++i) {
            int k = tid + 128 * i;
            mn = min(mn, g_bmin[k]);
            mx = max(mx, g_bmax[k]);
        }
        #pragma unroll
        for (int o = 16; o; o >>= 1) {
            mn = min(mn, __shfl_xor_sync(0xFFFFFFFFu, mn, o));
            mx = max(mx, __shfl_xor_sync(0xFFFFFFFFu, mx, o));
        }
        if ((tid & 31) == 0) { smn[tid >> 5] = mn; smx[tid >> 5] = mx; }
    }

    // Zero never-filled last .y slots (finite; col mask forces w=0)
    if (tid < TROW) {
        sbx[tid][TCOL - 1].y = 0.f;
        sby[tid][TCOL - 1].y = 0.f;
    }
    if (tid < DROW) {
        sdx[tid][DCOL - 1].y = 0.f;
        sdy[tid][DCOL - 1].y = 0.f;
    }

    // Tile fill; out-of-range rows get sentinel x=1e19 (=> w=0), y=0
    for (int k = tid; k < TROW * TCOL; k += 128) {
        int r = k / TCOL, c = k % TCOL;
        int gi = by + r - 9;
        int gj = min(max(bx + c - 9, 0), 511);
        float vx = 1e19f, vy = 0.f;
        if ((unsigned)gi < 512u) {
            float2 v = g_base[(gi << 9) + gj];
            vx = v.x; vy = v.y;
        }
        sbx[r][c].x = vx;
        sby[r][c].x = vy;
        if (c > 0) { sbx[r][c - 1].y = vx; sby[r][c - 1].y = vy; }
    }
    for (int k = tid; k < DROW * DCOL; k += 128) {
        int r = k / DCOL, c = k % DCOL;
        int gi = by + r - 2;
        int gj = min(max(bx + c - 4, 0), 511);
        float vx = 1e19f, vy = 0.f;
        if ((unsigned)gi < 512u) {
            float2 v = g_det[(gi << 9) + gj];
            vx = v.x; vy = v.y;
        }
        sdx[r][c].x = vx;
        sdy[r][c].x = vy;
        if (c > 0) { sdx[r][c - 1].y = vx; sdy[r][c - 1].y = vy; }
    }
    __syncthreads();

    float Cs;
    {
        unsigned m = min(min(smn[0], smn[1]), min(smn[2], smn[3]));
        unsigned M = max(max(smx[0], smx[1]), max(smx[2], smx[3]));
        float sigma = R[0] * (key2f(M) - key2f(m));
        float h = sigma * 0.5f;
        Cs = -LOG2E / (h * h);
    }
    u64 C2; PACK2(C2, Cs, Cs);

    int ty2 = ty * 2;
    int gi0 = by + ty2;          // center rows gi0, gi0+1
    int gj  = bx + tx;

    // chunk window
    int kch = min((gj - 1) / 62, 8);
    int cs = 62 * kch;
    int ce = min(cs + 64, 512);

    const float invS1L = LOG2E / 8145.0625f;   // (19*19/4)^2
    const float invS0L = LOG2E / 126.5625f;    // (5*9/4)^2

    // ---------------- Base: 19x19, two centers ----------------
    float xc0 = sbx[ty2 + 9][tx + 9].x;
    float xc1 = sbx[ty2 + 10][tx + 9].x;
    u64 b10, b11;
    { float a = -2.f * Cs * xc0; PACK2(b10, a, a); }
    { float a = -2.f * Cs * xc1; PACK2(b11, a, a); }
    float cx0 = Cs * xc0 * xc0;
    float cx1 = Cs * xc1 * xc1;
    float dbs = -2.f * Cs * (xc1 - xc0);
    u64 db2; PACK2(db2, dbs, dbs);

    u64 Lb[10];
    {
        #pragma unroll
        for (int p = 0; p < 10; ++p) {
            float l0 = -1e30f, l1 = -1e30f;
            int dj0 = 2 * p, dj1 = 2 * p + 1;
            int j0 = gj - 9 + dj0, j1 = gj - 9 + dj1;
            if (j0 >= cs && j0 < ce) { int cc = dj0 - 9; l0 = -(float)(cc * cc) * invS1L; }
            if (dj1 < 19 && j1 >= cs && j1 < ce) { int cc = dj1 - 9; l1 = -(float)(cc * cc) * invS1L; }
            PACK2(Lb[p], l0, l1);
        }
    }

    u64 g0 = 0, g1 = 0, g2 = 0, g3 = 0, g4 = 0;      // center0
    u64 h0 = 0, h1 = 0, h2 = 0, h3 = 0, h4 = 0;      // center1

    // ---- peeled r = 0: center0 only ----
    {
        float k0 = -81.f * invS1L + cx0;
        u64 k02; PACK2(k02, k0, k0);
        const u64* rbx = (const u64*)&sbx[ty2][tx];
        const u64* rby = (const u64*)&sby[ty2][tx];
        #pragma unroll
        for (int p = 0; p < 10; ++p) {
            u64 vx2 = rbx[2 * p];
            u64 vy2 = rby[2 * p];
            u64 u, a, w;
            FMA2(u, C2, vx2, b10);
            FMA2(a, u, vx2, Lb[p]);
            ADD2(a, a, k02);
            EXP2PAIR(w, a);
            ACC5(g0, g1, g2, g3, g4, w, vx2, vy2);
        }
    }

    // ---- interior r = 1..18: both centers, delta exponent ----
    #pragma unroll 1
    for (int r = 1; r < 19; ++r) {
        float fd0 = (float)(r - 9), fd1 = (float)(r - 10);
        float lr0 = -fd0 * fd0 * invS1L;
        float lr1 = -fd1 * fd1 * invS1L;
        float k0 = lr0 + cx0;
        float dk = (lr1 + cx1) - k0;
        u64 k02; PACK2(k02, k0, k0);
        u64 dk2; PACK2(dk2, dk, dk);

        const u64* rbx = (const u64*)&sbx[ty2 + r][tx];
        const u64* rby = (const u64*)&sby[ty2 + r][tx];

        #pragma unroll
        for (int p = 0; p < 10; ++p) {
            u64 vx2 = rbx[2 * p];
            u64 vy2 = rby[2 * p];
            u64 u, a0q, a1q, t, w0q, w1q;
            FMA2(u, C2, vx2, b10);
            FMA2(a0q, u, vx2, Lb[p]);
            ADD2(a0q, a0q, k02);
            FMA2(t, db2, vx2, dk2);
            ADD2(a1q, a0q, t);
            EXP2PAIR(w0q, a0q);
            EXP2PAIR(w1q, a1q);
            ACC5(g0, g1, g2, g3, g4, w0q, vx2, vy2);
            ACC5(h0, h1, h2, h3, h4, w1q, vx2, vy2);
        }
    }

    // ---- peeled r = 19: center1 only ----
    {
        float k1 = -81.f * invS1L + cx1;
        u64 k12; PACK2(k12, k1, k1);
        const u64* rbx = (const u64*)&sbx[ty2 + 19][tx];
        const u64* rby = (const u64*)&sby[ty2 + 19][tx];
        #pragma unroll
        for (int p = 0; p < 10; ++p) {
            u64 vx2 = rbx[2 * p];
            u64 vy2 = rby[2 * p];
            u64 u, a, w;
            FMA2(u, C2, vx2, b11);
            FMA2(a, u, vx2, Lb[p]);
            ADD2(a, a, k12);
            EXP2PAIR(w, a);
            ACC5(h0, h1, h2, h3, h4, w, vx2, vy2);
        }
    }

    float A0, B0, A1, B1;
    {
        float a, b, sw, swx, swxx, swy, swxy;
        UNPACK2(a, b, g0); sw = a + b;
        UNPACK2(a, b, g1); swx = a + b;
        UNPACK2(a, b, g2); swxx = a + b;
        UNPACK2(a, b, g3); swy = a + b;
        UNPACK2(a, b, g4); swxy = a + b;
        float invsw = 1.0f / sw;
        float mx = swx * invsw, my = swy * invsw;
        float var = fmaf(-mx, mx, swxx * invsw);
        float cov = fmaf(-mx, my, swxy * invsw);
        A0 = cov / (var + 1e-6f);
        B0 = fmaf(-A0, mx, my);
    }
    {
        float a, b, sw, swx, swxx, swy, swxy;
        UNPACK2(a, b, h0); sw = a + b;
        UNPACK2(a, b, h1); swx = a + b;
        UNPACK2(a, b, h2); swxx = a + b;
        UNPACK2(a, b, h3); swy = a + b;
        UNPACK2(a, b, h4); swxy = a + b;
        float invsw = 1.0f / sw;
        float mx = swx * invsw, my = swy * invsw;
        float var = fmaf(-mx, mx, swxx * invsw);
        float cov = fmaf(-mx, my, swxy * invsw);
        A1 = cov / (var + 1e-6f);
        B1 = fmaf(-A1, mx, my);
    }

    // ---------------- Detail: 5x9, two centers, peel + delta ----------------
    u64 Ld[5];
    {
        #pragma unroll
        for (int p = 0; p < 5; ++p) {
            float l0 = -1e30f, l1 = -1e30f;
            int dj0 = 2 * p, dj1 = 2 * p + 1;
            int j0 = gj - 4 + dj0, j1 = gj - 4 + dj1;
            if (j0 >= cs && j0 < ce) { int cc = dj0 - 4; l0 = -(float)(cc * cc) * invS0L; }
            if (dj1 < 9 && j1 >= cs && j1 < ce) { int cc = dj1 - 4; l1 = -(float)(cc * cc) * invS0L; }
            PACK2(Ld[p], l0, l1);
        }
    }

    float xd0 = sdx[ty2 + 2][tx + 4].x;
    float xd1 = sdx[ty2 + 3][tx + 4].x;
    u64 bd0p, bd1p;
    { float a = -2.f * Cs * xd0; PACK2(bd0p, a, a); }
    { float a = -2.f * Cs * xd1; PACK2(bd1p, a, a); }
    float cxd0 = Cs * xd0 * xd0;
    float cxd1 = Cs * xd1 * xd1;
    float dbd = -2.f * Cs * (xd1 - xd0);
    u64 dbd2; PACK2(dbd2, dbd, dbd);

    u64 s00 = 0, s01 = 0, s10 = 0, s11 = 0;   // {center}{w|wz}

    // r = 0: center0 only
    {
        float k0 = -4.f * invS0L + cxd0;
        u64 k02; PACK2(k02, k0, k0);
        const u64* rdx = (const u64*)&sdx[ty2][tx];
        const u64* rdy = (const u64*)&sdy[ty2][tx];
        #pragma unroll
        for (int p = 0; p < 5; ++p) {
            u64 vx2 = rdx[2 * p];
            u64 vy2 = rdy[2 * p];
            u64 u, a, w;
            FMA2(u, C2, vx2, bd0p);
            FMA2(a, u, vx2, Ld[p]);
            ADD2(a, a, k02);
            EXP2PAIR(w, a);
            ADD2(s00, s00, w);
            FMA2(s01, w, vy2, s01);
        }
    }
    // r = 1..4: both centers, delta
    #pragma unroll
    for (int r = 1; r < 5; ++r) {
        float fd0 = (float)(r - 2), fd1 = (float)(r - 3);
        float lr0 = -fd0 * fd0 * invS0L;
        float lr1 = -fd1 * fd1 * invS0L;
        float k0 = lr0 + cxd0;
        float dk = (lr1 + cxd1) - k0;
        u64 k02; PACK2(k02, k0, k0);
        u64 dk2; PACK2(dk2, dk, dk);

        const u64* rdx = (const u64*)&sdx[ty2 + r][tx];
        const u64* rdy = (const u64*)&sdy[ty2 + r][tx];
        #pragma unroll
        for (int p = 0; p < 5; ++p) {
            u64 vx2 = rdx[2 * p];
            u64 vy2 = rdy[2 * p];
            u64 u, a0q, a1q, t, w0q, w1q;
            FMA2(u, C2, vx2, bd0p);
            FMA2(a0q, u, vx2, Ld[p]);
            ADD2(a0q, a0q, k02);
            FMA2(t, dbd2, vx2, dk2);
            ADD2(a1q, a0q, t);
            EXP2PAIR(w0q, a0q);
            EXP2PAIR(w1q, a1q);
            ADD2(s00, s00, w0q);
            FMA2(s01, w0q, vy2, s01);
            ADD2(s10, s10, w1q);
            FMA2(s11, w1q, vy2, s11);
        }
    }
    // r = 5: center1 only
    {
        float k1 = -4.f * invS0L + cxd1;
        u64 k12; PACK2(k12, k1, k1);
        const u64* rdx = (const u64*)&sdx[ty2 + 5][tx];
        const u64* rdy = (const u64*)&sdy[ty2 + 5][tx];
        #pragma unroll
        for (int p = 0; p < 5; ++p) {
            u64 vx2 = rdx[2 * p];
            u64 vy2 = rdy[2 * p];
            u64 u, a, w;
            FMA2(u, C2, vx2, bd1p);
            FMA2(a, u, vx2, Ld[p]);
            ADD2(a, a, k12);
            EXP2PAIR(w, a);
            ADD2(s10, s10, w);
            FMA2(s11, w, vy2, s11);
        }
    }

    float a, b, sw0, sz0, sw1, sz1;
    UNPACK2(a, b, s00); sw0 = a + b;
    UNPACK2(a, b, s01); sz0 = a + b;
    UNPACK2(a, b, s10); sw1 = a + b;
    UNPACK2(a, b, s11); sz1 = a + b;

    out[(gi0 << 9) + gj]       = fmaf(A0, xc0, B0 + xd0 + sz0 / sw0);
    out[((gi0 + 1) << 9) + gj] = fmaf(A1, xc1, B1 + xd1 + sz1 / sw1);
}

extern "C" void kernel_launch(void* const* d_in, const int* in_sizes, int n_in,
                              void* d_out, int out_size) {
    const float* X = (const float*)d_in[0];
    const float* Y = (const float*)d_in[1];
    const float* R = (const float*)d_in[2];
    float* out = (float*)d_out;

    k_pre<<<dim3(16, 64), dim3(32, 8)>>>(X, Y);
    k_main<<<dim3(16, 64), dim3(32, 4)>>>(R, out);
}